// round 8
// baseline (speedup 1.0000x reference)
#include <cuda_runtime.h>
#include <math.h>

#define Bb 4
#define Nn 32
#define Mm 64
#define Kk 16
#define K1 17
#define Pp 128
#define Ww 128
#define TWd 256

typedef unsigned long long ull;

// ---------- f32x2 helpers ----------
__device__ __forceinline__ ull pack2(float a, float b) {
    ull r; asm("mov.b64 %0, {%1, %2};" : "=l"(r) : "f"(a), "f"(b)); return r;
}
__device__ __forceinline__ void unpack2(ull v, float& a, float& b) {
    asm("mov.b64 {%0, %1}, %2;" : "=f"(a), "=f"(b) : "l"(v));
}
__device__ __forceinline__ void fma2(ull& d, ull a, ull b) {
    asm("fma.rn.f32x2 %0, %1, %2, %0;" : "+l"(d) : "l"(a), "l"(b));
}
__device__ __forceinline__ ull add2(ull a, ull b) {
    ull r; asm("add.rn.f32x2 %0, %1, %2;" : "=l"(r) : "l"(a), "l"(b)); return r;
}
// exact identity tanh = 1 - 2/(exp(2x)+1); only error is __expf rounding (~2^-21)
__device__ __forceinline__ float ftanh(float x) {
    float e = __expf(2.0f * x);
    return 1.0f - __fdividef(2.0f, e + 1.0f);
}

// ------- scratch (device globals; no runtime allocation) -------
__device__ float d_A[Bb*Nn*K1*TWd];
__device__ float d_Bm[Bb*Mm*TWd];
__device__ float d_gdot[Bb*Nn*Mm];
__device__ float d_sw0T[Ww*Ww];   // [w][i]
__device__ float d_sw1T[Ww*Ww];   // [w][i]

// =====================================================================
// K_tr: transpose sw0/sw1 for coalesced column access in stages 2/4
// =====================================================================
__global__ void k_tr(const float* __restrict__ sw0, const float* __restrict__ sw1)
{
    const int idx = blockIdx.x*256 + threadIdx.x;  // 0..16383
    const int i = idx >> 7, w = idx & 127;
    d_sw0T[w*Ww + i] = sw0[idx];
    d_sw1T[w*Ww + i] = sw1[idx];
}

// =====================================================================
// K1: attention MLP + softmax + coeff + A-partial.  One block per (b,n,k1).
// =====================================================================
__global__ void __launch_bounds__(128) k1_attn(
    const float* __restrict__ phase, const float* __restrict__ posc,
    const float* __restrict__ sigma, const float* __restrict__ velc,
    const float* __restrict__ aw0, const float* __restrict__ ab0,
    const float* __restrict__ aw1, const float* __restrict__ ab1,
    const float* __restrict__ aw2, const float* __restrict__ ab2,
    const float* __restrict__ tw0, const float* __restrict__ tb0)
{
    __shared__ float s_aw0[6*64];
    __shared__ float s_ab0[64];
    __shared__ float s_aw1[64*64];
    __shared__ float s_ab1[64];
    __shared__ float s_aw2[64];
    __shared__ float red[128];

    const int bx = blockIdx.x;
    const int k1 = bx % K1;
    const int n  = (bx / K1) % Nn;
    const int b  = bx / (K1*Nn);
    const int t  = threadIdx.x;

    for (int i = t; i < 6*64; i += 128) s_aw0[i] = aw0[i];
    if (t < 64) { s_ab0[t] = ab0[t]; s_aw2[t] = aw2[t]; s_ab1[t] = ab1[t]; }
    for (int i = t; i < 64*64; i += 128) s_aw1[i] = aw1[i];
    __syncthreads();

    const float x0 = phase[(b*Nn+n)*4 + 0];
    const float x1 = phase[(b*Nn+n)*4 + 1];
    float va0, va1;
    if (k1 == 0) { va0 = phase[(b*Nn+n)*4 + 2]; va1 = phase[(b*Nn+n)*4 + 3]; }
    else         { va0 = velc[(b*Kk + (k1-1))*2 + 0]; va1 = velc[(b*Kk + (k1-1))*2 + 1]; }
    const float inv = rsqrtf(va0*va0 + va1*va1 + 1e-16f);
    const float ag0 = va0*inv, ag1 = va1*inv;

    const float rx = x0 - posc[(b*Pp + t)*2 + 0];
    const float ry = x1 - posc[(b*Pp + t)*2 + 1];
    const float rd = sqrtf(rx*rx + ry*ry + 1e-16f);
    const float pl = rx*ag0 + ry*ag1;
    const float al = pl / (rd + 1e-8f);

    float h0[64];
#pragma unroll
    for (int j = 0; j < 64; j++) {
        h0[j] = ftanh(s_ab0[j] + x0*s_aw0[0*64+j] + x1*s_aw0[1*64+j]
                              + va0*s_aw0[2*64+j] + va1*s_aw0[3*64+j]
                              + al*s_aw0[4*64+j] + pl*s_aw0[5*64+j]);
    }
    float logit = ab2[0];
#pragma unroll
    for (int g = 0; g < 4; g++) {
        ull acc[8];
#pragma unroll
        for (int p = 0; p < 8; p++) acc[p] = 0ull;
        for (int j = 0; j < 64; j++) {
            const ull hp = pack2(h0[j], h0[j]);
            const float* wrow = &s_aw1[j*64 + g*16];
            ulonglong2 wA = *reinterpret_cast<const ulonglong2*>(wrow + 0);
            ulonglong2 wB = *reinterpret_cast<const ulonglong2*>(wrow + 4);
            ulonglong2 wC = *reinterpret_cast<const ulonglong2*>(wrow + 8);
            ulonglong2 wD = *reinterpret_cast<const ulonglong2*>(wrow + 12);
            fma2(acc[0], hp, wA.x); fma2(acc[1], hp, wA.y);
            fma2(acc[2], hp, wB.x); fma2(acc[3], hp, wB.y);
            fma2(acc[4], hp, wC.x); fma2(acc[5], hp, wC.y);
            fma2(acc[6], hp, wD.x); fma2(acc[7], hp, wD.y);
        }
#pragma unroll
        for (int p = 0; p < 8; p++) {
            const int i = g*16 + p*2;
            float a0, a1; unpack2(acc[p], a0, a1);
            logit += ftanh(a0 + s_ab1[i])   * s_aw2[i]
                   + ftanh(a1 + s_ab1[i+1]) * s_aw2[i+1];
        }
    }

    float lg = (pl > 0.0f) ? logit : -1e30f;
    red[t] = lg; __syncthreads();
    for (int s = 64; s > 0; s >>= 1) { if (t < s) red[t] = fmaxf(red[t], red[t+s]); __syncthreads(); }
    const float mx = red[0]; __syncthreads();
    const float e = __expf(lg - mx);
    red[t] = e; __syncthreads();
    for (int s = 64; s > 0; s >>= 1) { if (t < s) red[t] += red[t+s]; __syncthreads(); }
    const float denom = red[0]; __syncthreads();
    const float aw = e / denom;

    const float sg0 = sigma[(b*Pp+t)*2 + 0];
    const float sg1 = sigma[(b*Pp+t)*2 + 1];
    red[t] = aw*sg0; __syncthreads();
    for (int s = 64; s > 0; s >>= 1) { if (t < s) red[t] += red[t+s]; __syncthreads(); }
    const float sum0 = red[0]; __syncthreads();
    red[t] = aw*sg1; __syncthreads();
    for (int s = 64; s > 0; s >>= 1) { if (t < s) red[t] += red[t+s]; __syncthreads(); }
    const float sum1 = red[0]; __syncthreads();

    const float c0 = __expf(-sum0);
    const float c1 = __expf(-sum1);

    for (int tt = t; tt < TWd; tt += 128) {
        float a = tb0[tt]
                + x0*tw0[0*TWd+tt] + x1*tw0[1*TWd+tt]
                + va0*tw0[2*TWd+tt] + va1*tw0[3*TWd+tt]
                + c0*tw0[8*TWd+tt] + c1*tw0[9*TWd+tt];
        d_A[bx*TWd + tt] = a;
    }
}

// =====================================================================
__global__ void k_bm(const float* __restrict__ bcoords, const float* __restrict__ tw0)
{
    const int bm = blockIdx.x;
    const int t  = threadIdx.x;
    const float xp0 = bcoords[bm*4+0], xp1 = bcoords[bm*4+1];
    const float vp0 = bcoords[bm*4+2], vp1 = bcoords[bm*4+3];
    d_Bm[bm*TWd + t] = xp0*tw0[4*TWd+t] + xp1*tw0[5*TWd+t]
                     + vp0*tw0[6*TWd+t] + vp1*tw0[7*TWd+t];
}

// =====================================================================
// K4: transport MLP + scattering chain.
//  - layer1: k-split x2 across thread halves + 4 cols/thread ->
//    26 wf per 72 fma2 per warp-step: FMA-bound.
//  - layer2/stage2: k-split x4 (5/4/4/4 rows) + 4 cols/thread.
//  - stage1: g row cached in registers, paired ws2 loads.
// =====================================================================
__global__ void __launch_bounds__(128, 4) k4_main(
    const float* __restrict__ scat, const float* __restrict__ sscat,
    const float* __restrict__ vwt,
    const float* __restrict__ tw1, const float* __restrict__ tb1,
    const float* __restrict__ tw2, const float* __restrict__ tb2,
    const float* __restrict__ sb0, const float* __restrict__ sb1,
    const float* __restrict__ out_w)
{
    __shared__ float buf[8704];      // h0(17x512) -> h1(17x512) -> [g(17x256)|rr(17x256)]
    __shared__ ull   ws2[272];
    __shared__ float sres[256];
    __shared__ float sred[8];

    const int bx   = blockIdx.x;              // 0..2047
    const int quad = bx & 15;                 // 2 m-pairs per block
    const int n    = (bx >> 4) & 31;
    const int b    = bx >> 9;
    const int t    = threadIdx.x;             // 0..127
    const int th   = t >> 6;                  // layer1 half
    const int tc   = t & 63;
    const int kb1  = th ? 9 : 0;              // layer1 k base
    const int kc1  = th ? 8 : 9;              // layer1 k count
    const int q    = t >> 5;                  // layer2/stage2 quarter
    const int tq   = t & 31;
    const int kb2  = q ? (1 + 4*q) : 0;       // 0,5,9,13
    const int kc2  = q ? 4 : 5;

    for (int i = t; i < 272; i += 128) {
        const int row = i >> 4, j = i & 15;
        float v = (row == 0) ? (1.0f - scat[(b*Nn+n)*Kk + j])
                             : (1.0f - sscat[b*256 + (row-1)*Kk + j]);
        v *= vwt[b*Kk + j];
        ws2[i] = pack2(v, v);
    }

    const float* Arow = d_A + (b*Nn + n)*K1*TWd;
    float tbv1[4], tbv2[4], sbv0[4];
#pragma unroll
    for (int c = 0; c < 4; c++) {
        tbv1[c] = tb1[tc + 64*c];
        tbv2[c] = tb2[tq + 32*c];
        sbv0[c] = sb0[tq + 32*c];
    }
    const float sb1c = sb1[t];
    const float owc  = out_w[t];

    for (int mm = 0; mm < 2; mm++) {
        const int pair = quad*2 + mm;

        // ---- layer 0: h0 pairs (cols t, t+128) ----
        {
            const float* bm0 = d_Bm + (b*Mm + pair*2 + 0)*TWd;
            const float* bm1 = bm0 + TWd;
            const float b0a = bm0[t], b0b = bm0[t+128];
            const float b1a = bm1[t], b1b = bm1[t+128];
#pragma unroll
            for (int k = 0; k < K1; k++) {
                const float A0 = Arow[k*TWd + t];
                const float A1 = Arow[k*TWd + t + 128];
                *reinterpret_cast<ull*>(buf + k*512 + 2*t) =
                    pack2(ftanh(A0 + b0a), ftanh(A0 + b1a));
                *reinterpret_cast<ull*>(buf + k*512 + 2*(t+128)) =
                    pack2(ftanh(A1 + b0b), ftanh(A1 + b1b));
            }
        }
        __syncthreads();

        // ---- layer 1: k-split halves, 4 cols (tc+64c); j-step 2 prefetch ----
        {
            ull acc[9][4];
#pragma unroll
            for (int k = 0; k < 9; k++)
#pragma unroll
                for (int c = 0; c < 4; c++) acc[k][c] = 0ull;
            const float* wb = tw1 + tc;
            float wc[8], wn[8];
#pragma unroll
            for (int jj = 0; jj < 2; jj++)
#pragma unroll
                for (int c = 0; c < 4; c++) wc[jj*4+c] = wb[jj*TWd + 64*c];
#pragma unroll 1
            for (int j = 0; j < TWd; j += 2) {
                if (j + 2 < TWd) {
                    const float* wp = wb + (j+2)*TWd;
#pragma unroll
                    for (int jj = 0; jj < 2; jj++)
#pragma unroll
                        for (int c = 0; c < 4; c++) wn[jj*4+c] = wp[jj*TWd + 64*c];
                }
                ull pw[8];
#pragma unroll
                for (int i = 0; i < 8; i++) pw[i] = pack2(wc[i], wc[i]);
#pragma unroll
                for (int k = 0; k < 9; k++) {
                    if (k < kc1) {
                        ulonglong2 ha = *reinterpret_cast<const ulonglong2*>(buf + (kb1+k)*512 + j*2);
#pragma unroll
                        for (int c = 0; c < 4; c++) {
                            fma2(acc[k][c], ha.x, pw[c]);
                            fma2(acc[k][c], ha.y, pw[4+c]);
                        }
                    }
                }
#pragma unroll
                for (int p = 0; p < 8; p++) wc[p] = wn[p];
            }
            __syncthreads();   // all h0 reads done -> overwrite with h1
#pragma unroll
            for (int k = 0; k < 9; k++) {
                if (k < kc1) {
#pragma unroll
                    for (int c = 0; c < 4; c++) {
                        float x0, x1; unpack2(acc[k][c], x0, x1);
                        *reinterpret_cast<ull*>(buf + (kb1+k)*512 + 2*(tc + 64*c)) =
                            pack2(ftanh(x0+tbv1[c]), ftanh(x1+tbv1[c]));
                    }
                }
            }
            __syncthreads();
        }

        // ---- layer 2: k-split quarters, 4 cols (tq+32c); j-step 2 prefetch ----
        {
            ull acc[5][4];
#pragma unroll
            for (int k = 0; k < 5; k++)
#pragma unroll
                for (int c = 0; c < 4; c++) acc[k][c] = 0ull;
            const float* wb = tw2 + tq;
            float wc[8], wn[8];
#pragma unroll
            for (int jj = 0; jj < 2; jj++)
#pragma unroll
                for (int c = 0; c < 4; c++) wc[jj*4+c] = wb[jj*Ww + 32*c];
#pragma unroll 1
            for (int j = 0; j < TWd; j += 2) {
                if (j + 2 < TWd) {
                    const float* wp = wb + (j+2)*Ww;
#pragma unroll
                    for (int jj = 0; jj < 2; jj++)
#pragma unroll
                        for (int c = 0; c < 4; c++) wn[jj*4+c] = wp[jj*Ww + 32*c];
                }
                ull pw[8];
#pragma unroll
                for (int i = 0; i < 8; i++) pw[i] = pack2(wc[i], wc[i]);
#pragma unroll
                for (int k = 0; k < 5; k++) {
                    if (k < kc2) {
                        ulonglong2 ha = *reinterpret_cast<const ulonglong2*>(buf + (kb2+k)*512 + j*2);
#pragma unroll
                        for (int c = 0; c < 4; c++) {
                            fma2(acc[k][c], ha.x, pw[c]);
                            fma2(acc[k][c], ha.y, pw[4+c]);
                        }
                    }
                }
#pragma unroll
                for (int p = 0; p < 8; p++) wc[p] = wn[p];
            }
            __syncthreads();   // all h1 reads done -> buf becomes [g | rr]
#pragma unroll
            for (int k = 0; k < 5; k++) {
                if (k < kc2) {
#pragma unroll
                    for (int c = 0; c < 4; c++) {
                        float x0, x1; unpack2(acc[k][c], x0, x1);
                        *reinterpret_cast<ull*>(buf + (kb2+k)*256 + 2*(tq + 32*c)) =
                            pack2(__expf(ftanh(x0+tbv2[c])), __expf(ftanh(x1+tbv2[c])));
                    }
                }
            }
            __syncthreads();
        }

        // ---- stage 1: rr[k] = sum_j ws2[k][j]*g[1+j]; g row cached in regs ----
        {
            ull g2r[Kk];
#pragma unroll
            for (int j = 0; j < Kk; j++)
                g2r[j] = *reinterpret_cast<const ull*>(buf + (1+j)*256 + 2*t);
#pragma unroll
            for (int k = 0; k < K1; k++) {
                ull r = 0ull;
                const ulonglong2* wsp = reinterpret_cast<const ulonglong2*>(ws2 + k*Kk);
#pragma unroll
                for (int jp = 0; jp < 8; jp++) {
                    const ulonglong2 wv = wsp[jp];
                    fma2(r, g2r[2*jp],   wv.x);
                    fma2(r, g2r[2*jp+1], wv.y);
                }
                *reinterpret_cast<ull*>(buf + 4352 + k*256 + 2*t) = r;
            }
            __syncthreads();
        }

        // ---- stage 2: g[k][c] += tanh(sw0T[:,c]@rr[k][:] + sb0[c]); k-quarters, 4 cols ----
        {
            ull s[5][4];
#pragma unroll
            for (int k = 0; k < 5; k++)
#pragma unroll
                for (int c = 0; c < 4; c++) s[k][c] = 0ull;
            const float* wb = d_sw0T + tq;
            float wc[8], wn[8];
#pragma unroll
            for (int ww = 0; ww < 2; ww++)
#pragma unroll
                for (int c = 0; c < 4; c++) wc[ww*4+c] = wb[ww*Ww + 32*c];
#pragma unroll 1
            for (int w = 0; w < Ww; w += 2) {
                if (w + 2 < Ww) {
                    const float* wp = wb + (w+2)*Ww;
#pragma unroll
                    for (int ww = 0; ww < 2; ww++)
#pragma unroll
                        for (int c = 0; c < 4; c++) wn[ww*4+c] = wp[ww*Ww + 32*c];
                }
                ull pw[8];
#pragma unroll
                for (int i = 0; i < 8; i++) pw[i] = pack2(wc[i], wc[i]);
#pragma unroll
                for (int k = 0; k < 5; k++) {
                    if (k < kc2) {
                        ulonglong2 ra = *reinterpret_cast<const ulonglong2*>(buf + 4352 + (kb2+k)*256 + w*2);
#pragma unroll
                        for (int c = 0; c < 4; c++) {
                            fma2(s[k][c], ra.x, pw[c]);
                            fma2(s[k][c], ra.y, pw[4+c]);
                        }
                    }
                }
#pragma unroll
                for (int p = 0; p < 8; p++) wc[p] = wn[p];
            }
#pragma unroll
            for (int k = 0; k < 5; k++) {
                if (k < kc2) {
#pragma unroll
                    for (int c = 0; c < 4; c++) {
                        float a0, a1; unpack2(s[k][c], a0, a1);
                        ull* gp = reinterpret_cast<ull*>(buf + (kb2+k)*256 + 2*(tq + 32*c));
                        float g0, g1; unpack2(*gp, g0, g1);
                        *gp = pack2(g0 + ftanh(a0+sbv0[c]), g1 + ftanh(a1+sbv0[c]));
                    }
                }
            }
            __syncthreads();
        }

        // ---- stage 3: resv2[t] = sum_k rw_v[k] * g'[1+k][t] ----
        {
            ull rv = 0ull;
#pragma unroll
            for (int k = 0; k < Kk; k++)
                fma2(rv, *reinterpret_cast<const ull*>(buf + (1+k)*256 + 2*t), ws2[k]);
            *reinterpret_cast<ull*>(sres + 2*t) = rv;
        }
        __syncthreads();

        // ---- stage 4: green = g'[0] + tanh(sw1T[:,t]@resv2 + sb1); gdot ----
        {
            ull sa = 0ull, sb = 0ull;
            const float* wb = d_sw1T + t;
#pragma unroll 1
            for (int w = 0; w < Ww; w += 4) {
                const float v0w = wb[(w+0)*Ww];
                const float v1w = wb[(w+1)*Ww];
                const float v2w = wb[(w+2)*Ww];
                const float v3w = wb[(w+3)*Ww];
                ulonglong2 ra = *reinterpret_cast<const ulonglong2*>(sres + w*2);
                ulonglong2 rb = *reinterpret_cast<const ulonglong2*>(sres + w*2 + 4);
                fma2(sa, ra.x, pack2(v0w,v0w)); fma2(sb, ra.y, pack2(v1w,v1w));
                fma2(sa, rb.x, pack2(v2w,v2w)); fma2(sb, rb.y, pack2(v3w,v3w));
            }
            const ull tot = add2(sa, sb);
            float a0, a1; unpack2(tot, a0, a1);
            float v0, v1; unpack2(*reinterpret_cast<const ull*>(buf + 2*t), v0, v1);
            float p0 = (v0 + ftanh(a0+sb1c)) * owc;
            float p1 = (v1 + ftanh(a1+sb1c)) * owc;
#pragma unroll
            for (int o = 16; o > 0; o >>= 1) {
                p0 += __shfl_down_sync(0xffffffffu, p0, o);
                p1 += __shfl_down_sync(0xffffffffu, p1, o);
            }
            if ((t & 31) == 0) { sred[(t>>5)*2] = p0; sred[(t>>5)*2+1] = p1; }
            __syncthreads();
            if (t == 0) {
                d_gdot[(b*Nn+n)*Mm + pair*2 + 0] = sred[0]+sred[2]+sred[4]+sred[6];
                d_gdot[(b*Nn+n)*Mm + pair*2 + 1] = sred[1]+sred[3]+sred[5]+sred[7];
            }
            __syncthreads();
        }
    }
}

// =====================================================================
__global__ void k6_final(const float* __restrict__ boundary,
                         const float* __restrict__ bweights,
                         float* __restrict__ out)
{
    __shared__ float s2[2];
    const int bn = blockIdx.x;
    const int b  = bn >> 5;
    const int t  = threadIdx.x;
    float v = d_gdot[bn*Mm + t] * boundary[b*Mm + t] * bweights[b*Mm + t];
#pragma unroll
    for (int o = 16; o > 0; o >>= 1) v += __shfl_down_sync(0xffffffffu, v, o);
    if ((t & 31) == 0) s2[t >> 5] = v;
    __syncthreads();
    if (t == 0) out[bn] = s2[0] + s2[1];
}

// =====================================================================
extern "C" void kernel_launch(void* const* d_in, const int* in_sizes, int n_in,
                              void* d_out, int out_size)
{
    const float* phase    = (const float*)d_in[0];
    const float* bcoords  = (const float*)d_in[1];
    const float* boundary = (const float*)d_in[2];
    const float* bweights = (const float*)d_in[3];
    const float* posc     = (const float*)d_in[4];
    const float* sigma    = (const float*)d_in[5];
    const float* velc     = (const float*)d_in[6];
    const float* vwt      = (const float*)d_in[7];
    const float* scat     = (const float*)d_in[8];
    const float* sscat    = (const float*)d_in[9];
    const float* aw0 = (const float*)d_in[10];
    const float* ab0 = (const float*)d_in[11];
    const float* aw1 = (const float*)d_in[12];
    const float* ab1 = (const float*)d_in[13];
    const float* aw2 = (const float*)d_in[14];
    const float* ab2 = (const float*)d_in[15];
    const float* tw0 = (const float*)d_in[16];
    const float* tb0 = (const float*)d_in[17];
    const float* tw1 = (const float*)d_in[18];
    const float* tb1 = (const float*)d_in[19];
    const float* tw2 = (const float*)d_in[20];
    const float* tb2 = (const float*)d_in[21];
    const float* sw0 = (const float*)d_in[22];
    const float* sb0 = (const float*)d_in[23];
    const float* sw1 = (const float*)d_in[24];
    const float* sb1 = (const float*)d_in[25];
    const float* ow  = (const float*)d_in[26];
    float* out = (float*)d_out;

    k_tr<<<64, 256>>>(sw0, sw1);
    k1_attn<<<Bb*Nn*K1, 128>>>(phase, posc, sigma, velc,
                               aw0, ab0, aw1, ab1, aw2, ab2, tw0, tb0);
    k_bm<<<Bb*Mm, TWd>>>(bcoords, tw0);
    k4_main<<<Bb*Nn*(Mm/4), 128>>>(
        scat, sscat, vwt, tw1, tb1, tw2, tb2, sb0, sb1, ow);
    k6_final<<<Bb*Nn, 64>>>(boundary, bweights, out);
}